// round 10
// baseline (speedup 1.0000x reference)
#include <cuda_runtime.h>

// x: (8, 64, 128, 128) fp32  ->  out: (8, 64, 384, 384) fp32
//
// Row dedup: distinct output rows are center(i)=Hresample(x[i]) -> row 3i+1,
// avg(i)=Hresample(0.5*(x[i]+x[i+1])) -> rows 3i+2 and 3i+3; row 0 = avg(0),
// rows 382/383 = center(127)/avg(126).
// Hresample: out col 3j+kj: kj=0 -> h[j-1], kj=1 -> c[j], kj=2 -> h[j];
// h[j] = 0.5*(c[j]+c[refl(j+1)]); reflect: -1 -> 1, 128 -> 126.
//
// R10: same converged R7 structure, but output stores use 256-bit
// st.global.cs.v8.f32 (sm_100+) for the first 1024B of each row
// (lane-contiguous, one full 32B sector per lane per instruction) plus one
// STG.128 for the 512B tail. 6 store instrs/warp instead of 9.

#define H 128
#define W 128
#define W4 (W / 4)
#define OW 384
#define OW4 (OW / 4)
#define NW 8
#define CPAD 144              // 128 + 4 pad per 32 floats (keeps 16B align)

__device__ __forceinline__ int swz(int j) { return j + ((j >> 5) << 2); }

struct GIdx { int aq, aq1, at, r; };

__device__ __forceinline__ GIdx gidx(int g)
{
    const int fg = g << 2;
    const int q  = (int)(((unsigned)fg * 21846u) >> 16);  // fg/3 (exact, fg<=380)
    const int r  = fg - 3 * q;
    const int qt = (r == 0) ? ((q == 0) ? 1 : q - 1)
                            : ((q >= W - 2) ? (W - 2) : q + 2);
    GIdx o;
    o.aq  = swz(q);
    o.aq1 = swz(q + 1);
    o.at  = swz(qt);
    o.r   = r;
    return o;
}

__device__ __forceinline__ float4 gatherv(const float* __restrict__ C,
                                          const GIdx& ix)
{
    const float cq  = C[ix.aq];
    const float cq1 = C[ix.aq1];
    const float ct  = C[ix.at];
    const int   r   = ix.r;

    const float h0 = 0.5f * (cq + cq1);
    const float ex = 0.5f * (ct + ((r == 0) ? cq : cq1));

    float4 v;
    v.x = (r == 0) ? ex  : ((r == 1) ? cq  : h0);
    v.y = (r == 0) ? cq  : h0;
    v.z = (r == 2) ? cq1 : h0;
    v.w = (r == 2) ? ex  : ((r == 1) ? cq1 : h0);
    return v;
}

__device__ __forceinline__ void stcs_v8(float* p, float4 a, float4 b)
{
    asm volatile(
        "st.global.cs.v8.f32 [%0], {%1,%2,%3,%4,%5,%6,%7,%8};"
        :: "l"(p),
           "f"(a.x), "f"(a.y), "f"(a.z), "f"(a.w),
           "f"(b.x), "f"(b.y), "f"(b.z), "f"(b.w)
        : "memory");
}

__global__ __launch_bounds__(NW * 32) void rf_scale_kernel(
    const float4* __restrict__ x, float4* __restrict__ out)
{
    __shared__ float Cs[NW][2][CPAD];   // [0] = center row, [1] = avg row

    const int lane = threadIdx.x & 31;
    const int w    = threadIdx.x >> 5;

    const int i  = blockIdx.x * NW + w;          // input row 0..127
    const int bc = blockIdx.y;

    const float4* __restrict__ xin = x + (size_t)bc * (H * W4);

    // i<127: avg(i) with row i+1; i==127: compute avg(126) for row 383.
    const int i1 = (i < H - 1) ? i + 1 : i - 1;
    const float4 b = xin[i  * W4 + lane];
    const float4 d = xin[i1 * W4 + lane];

    float4 av;
    av.x = 0.5f * (b.x + d.x);
    av.y = 0.5f * (b.y + d.y);
    av.z = 0.5f * (b.z + d.z);
    av.w = 0.5f * (b.w + d.w);

    const int so = swz(lane << 2);
    *reinterpret_cast<float4*>(&Cs[w][0][so]) = b;
    *reinterpret_cast<float4*>(&Cs[w][1][so]) = av;
    __syncwarp();

    const float* __restrict__ Cc = Cs[w][0];
    const float* __restrict__ Ca = Cs[w][1];

    // Three gather positions per row: float8 chunk (g=2*lane, 2*lane+1)
    // covering floats 0..255, and float4 tail at g=64+lane (floats 256..383).
    const GIdx iA = gidx(2 * lane);
    const GIdx iB = gidx(2 * lane + 1);
    const GIdx iC = gidx(64 + lane);

    const float4 cA = gatherv(Cc, iA);
    const float4 cB = gatherv(Cc, iB);
    const float4 cC = gatherv(Cc, iC);

    const float4 aA = gatherv(Ca, iA);
    const float4 aB = gatherv(Ca, iB);
    const float4 aC = gatherv(Ca, iC);

    float4* __restrict__ obase =
        out + (size_t)bc * (OW * OW4) + (size_t)(3 * i) * OW4;

    const bool last = (i == H - 1);

    // center(i) -> row 3i+1
    {
        float* rowp = reinterpret_cast<float*>(obase + OW4);
        stcs_v8(rowp + 8 * lane, cA, cB);
        __stcs(reinterpret_cast<float4*>(rowp) + 64 + lane, cC);
    }

    // avg -> row 3i+2 (always; for i==127 this is row 383 = avg(126))
    {
        float* rowp = reinterpret_cast<float*>(obase + 2 * OW4);
        stcs_v8(rowp + 8 * lane, aA, aB);
        __stcs(reinterpret_cast<float4*>(rowp) + 64 + lane, aC);
    }

    if (!last) {
        // avg -> row 3i+3
        float* rowp = reinterpret_cast<float*>(obase + 3 * OW4);
        stcs_v8(rowp + 8 * lane, aA, aB);
        __stcs(reinterpret_cast<float4*>(rowp) + 64 + lane, aC);

        if (i == 0) {      // row 0 = avg(0)
            float* r0 = reinterpret_cast<float*>(obase);
            stcs_v8(r0 + 8 * lane, aA, aB);
            __stcs(reinterpret_cast<float4*>(r0) + 64 + lane, aC);
        }
    }
}

extern "C" void kernel_launch(void* const* d_in, const int* in_sizes, int n_in,
                              void* d_out, int out_size)
{
    const float4* x = (const float4*)d_in[0];
    float4* out = (float4*)d_out;

    const int n_bc = in_sizes[0] / (H * W);   // 512

    dim3 grid(H / NW, n_bc);                  // (16, 512)
    dim3 block(NW * 32);                      // 256
    rf_scale_kernel<<<grid, block>>>(x, out);
}

// round 11
// speedup vs baseline: 1.0500x; 1.0500x over previous
#include <cuda_runtime.h>

// x: (8, 64, 128, 128) fp32  ->  out: (8, 64, 384, 384) fp32
//
// FINAL (converged R7 design; best measured 51.2us, HBM write-stream bound).
//
// Math: with RATIO=0.5, KS=3, the reference collapses to a separable
// 3x nearest/half-pixel resample. Row dedup: out[3i] == out[3(i-1)+2], so the
// distinct output rows are:
//   center(i) = Hresample(x[i])              -> row 3i+1
//   avg(i)    = Hresample(0.5*(x[i]+x[i+1])) -> rows 3i+2 and 3i+3
//   row 0 = avg(0), row 383 = avg(126)   (reflect padding at borders)
// Hresample: out col 3j+kj: kj=0 -> h[j-1], kj=1 -> c[j], kj=2 -> h[j];
// h[j] = 0.5*(c[j]+c[refl(j+1)]); reflect: -1 -> 1, 128 -> 126.
//
// Design: warp per input row i.
//  - 2x LDG.128 (default policy: row i+1 L1-hits for the adjacent warp)
//  - vertical blend in regs, 2x STS.128 into bank-conflict-free padded smem
//  - gather indices (q, r, reflect) computed ONCE per output float4 and
//    reused for both the center and avg rows (avg gathered once, stored to
//    both duplicate destination rows)
//  - all output stores: coalesced, full-sector STG.128 .cs (streaming,
//    evict-first; 302MB output is write-once)
// Validated ceiling: LSU STG.128 / TMA bulk store / STG.256 all pin DRAM at
// 68-70% -> L2/HBM write-turnaround limit, not an SM-side resource.

#define H 128
#define W 128
#define W4 (W / 4)
#define OW 384
#define OW4 (OW / 4)
#define NW 8
#define CPAD 144              // 128 + 4 pad per 32 floats (keeps 16B align)

__device__ __forceinline__ int swz(int j) { return j + ((j >> 5) << 2); }

__device__ __forceinline__ float4 gatherv(const float* __restrict__ C,
                                          int aq, int aq1, int at, int r)
{
    const float cq  = C[aq];
    const float cq1 = C[aq1];
    const float ct  = C[at];

    const float h0 = 0.5f * (cq + cq1);
    const float ex = 0.5f * (ct + ((r == 0) ? cq : cq1));

    float4 v;
    v.x = (r == 0) ? ex  : ((r == 1) ? cq  : h0);
    v.y = (r == 0) ? cq  : h0;
    v.z = (r == 2) ? cq1 : h0;
    v.w = (r == 2) ? ex  : ((r == 1) ? cq1 : h0);
    return v;
}

__global__ __launch_bounds__(NW * 32) void rf_scale_kernel(
    const float4* __restrict__ x, float4* __restrict__ out)
{
    __shared__ float Cs[NW][2][CPAD];   // [0] = center row, [1] = avg row

    const int lane = threadIdx.x & 31;
    const int w    = threadIdx.x >> 5;

    const int i  = blockIdx.x * NW + w;          // input row 0..127
    const int bc = blockIdx.y;

    const float4* __restrict__ xin = x + (size_t)bc * (H * W4);

    // i<127: avg(i) with row i+1; i==127: compute avg(126) for row 383.
    const int i1 = (i < H - 1) ? i + 1 : i - 1;
    const float4 b = xin[i  * W4 + lane];
    const float4 d = xin[i1 * W4 + lane];

    float4 av;
    av.x = 0.5f * (b.x + d.x);
    av.y = 0.5f * (b.y + d.y);
    av.z = 0.5f * (b.z + d.z);
    av.w = 0.5f * (b.w + d.w);

    const int so = swz(lane << 2);
    *reinterpret_cast<float4*>(&Cs[w][0][so]) = b;
    *reinterpret_cast<float4*>(&Cs[w][1][so]) = av;
    __syncwarp();

    const float* __restrict__ Cc = Cs[w][0];
    const float* __restrict__ Ca = Cs[w][1];

    float4* __restrict__ obase =
        out + (size_t)bc * (OW * OW4) + (size_t)(3 * i) * OW4;

    const bool last = (i == H - 1);

    #pragma unroll
    for (int s = 0; s < 3; s++) {
        const int g  = lane + (s << 5);                       // 0..95
        const int fg = g << 2;
        const int q  = (int)(((unsigned)fg * 21846u) >> 16);  // fg/3 (exact)
        const int r  = fg - 3 * q;

        const int qt = (r == 0) ? ((q == 0) ? 1 : q - 1)
                                : ((q == W - 2) ? (W - 2) : q + 2);

        const int aq  = swz(q);
        const int aq1 = swz(q + 1);
        const int at  = swz(qt);

        // center(i) -> row 3i+1
        __stcs(&obase[OW4 + g], gatherv(Cc, aq, aq1, at, r));

        const float4 v = gatherv(Ca, aq, aq1, at, r);
        if (!last) {
            __stcs(&obase[2 * OW4 + g], v);           // row 3i+2 = avg(i)
            __stcs(&obase[3 * OW4 + g], v);           // row 3i+3 = avg(i)
            if (i == 0) __stcs(&obase[g], v);         // row 0    = avg(0)
        } else {
            __stcs(&obase[2 * OW4 + g], v);           // row 383  = avg(126)
        }
    }
}

extern "C" void kernel_launch(void* const* d_in, const int* in_sizes, int n_in,
                              void* d_out, int out_size)
{
    const float4* x = (const float4*)d_in[0];
    float4* out = (float4*)d_out;

    const int n_bc = in_sizes[0] / (H * W);   // 512

    dim3 grid(H / NW, n_bc);                  // (16, 512)
    dim3 block(NW * 32);                      // 256
    rf_scale_kernel<<<grid, block>>>(x, out);
}